// round 5
// baseline (speedup 1.0000x reference)
#include <cuda_runtime.h>
#include <math.h>
#include <stdint.h>

#define NB   8192
#define NA   32
#define NOBS 128
#define NH1  128
#define NHX  64
#define NACT 16

#define BT   64
#define PAD  68   // padded row stride, multiple of 4 -> 16B-aligned LDS.128 rows

typedef unsigned long long u64;

// Scratch (allocation-free rule: __device__ globals)
__device__ float g_h[NB * NA * NHX];      // 64 MB
__device__ float g_comm[NB * NA * NHX];   // 64 MB
__device__ float g_maskn[NA * NA];

// ---------------- f32x2 / LDS helpers ----------------
__device__ __forceinline__ uint32_t sptr(const void* p) {
    return (uint32_t)__cvta_generic_to_shared(p);
}
__device__ __forceinline__ u64 pk2(float x) {           // duplicate into pair
    u64 r; asm("mov.b64 %0, {%1, %1};" : "=l"(r) : "f"(x)); return r;
}
__device__ __forceinline__ u64 mk2(float x, float y) {  // pack two floats
    u64 r; asm("mov.b64 %0, {%1, %2};" : "=l"(r) : "f"(x), "f"(y)); return r;
}
__device__ __forceinline__ float2 up2(u64 a) {
    float2 f; asm("mov.b64 {%0, %1}, %2;" : "=f"(f.x), "=f"(f.y) : "l"(a)); return f;
}
__device__ __forceinline__ void ffma2(u64 &d, u64 a, u64 b) {
    asm("fma.rn.f32x2 %0, %1, %2, %3;" : "=l"(d) : "l"(a), "l"(b), "l"(d));
}
__device__ __forceinline__ void lds128_2x64(u64 &a, u64 &b, uint32_t addr) {
    asm volatile("ld.shared.v2.u64 {%0, %1}, [%2];" : "=l"(a), "=l"(b) : "r"(addr));
}
__device__ __forceinline__ void lds128_f4(float4 &v, uint32_t addr) {
    asm volatile("ld.shared.v4.f32 {%0,%1,%2,%3}, [%4];"
                 : "=f"(v.x), "=f"(v.y), "=f"(v.z), "=f"(v.w) : "r"(addr));
}
__device__ __forceinline__ void lds64_f2(float2 &v, uint32_t addr) {
    asm volatile("ld.shared.v2.f32 {%0,%1}, [%2];" : "=f"(v.x), "=f"(v.y) : "r"(addr));
}
__device__ __forceinline__ void sts128_2x64(uint32_t addr, u64 a, u64 b) {
    asm volatile("st.shared.v2.u64 [%0], {%1, %2};" :: "r"(addr), "l"(a), "l"(b));
}
__device__ __forceinline__ u64 relu2(u64 a) {
    float2 f = up2(a);
    return mk2(fmaxf(f.x, 0.0f), fmaxf(f.y, 0.0f));
}
__device__ __forceinline__ u64 tanh2(u64 a) {
    float2 f = up2(a);
    return mk2(tanhf(f.x), tanhf(f.y));
}

// ---------------------------------------------------------------------------
// Normalized communication matrix: M[i][j] = offdiag_mask / max(count_i, 1)
// ---------------------------------------------------------------------------
__global__ void k_mask(const int* __restrict__ cm) {
    int i = threadIdx.x;
    if (i >= NA) return;
    int cnt = 0;
#pragma unroll
    for (int j = 0; j < NA; j++)
        cnt += (j != i && cm[i * NA + j] != 0) ? 1 : 0;
    float inv = 1.0f / (float)(cnt > 0 ? cnt : 1);
#pragma unroll
    for (int j = 0; j < NA; j++)
        g_maskn[i * NA + j] = (j != i && cm[i * NA + j] != 0) ? inv : 0.0f;
}

// ---------------------------------------------------------------------------
// Encoder: h = relu(relu(obs@W1 + b1)@W2 + b2), per (batch-tile, agent) block
// ---------------------------------------------------------------------------
__global__ __launch_bounds__(256, 2) void k_encode(
    const float* __restrict__ obs,
    const float* __restrict__ W1, const float* __restrict__ b1,
    const float* __restrict__ W2, const float* __restrict__ b2)
{
    extern __shared__ float sm[];
    float* Ws   = sm;                       // 128*128 floats (W1, then W2)
    float* aT   = sm + NH1 * NOBS;          // 128 x PAD
    float* bias = aT + NOBS * PAD;          // 128

    const int tid = threadIdx.x;
    const int b0  = blockIdx.x * BT;
    const int a   = blockIdx.y;

    // Stage W1 [k][n] row-major
    {
        const float4* src = (const float4*)(W1 + a * NOBS * NH1);
        float4* dst = (float4*)Ws;
#pragma unroll
        for (int i = tid; i < NOBS * NH1 / 4; i += 256) dst[i] = src[i];
    }
    // Stage obs transposed: aT[k][m] = obs[b0+m][a][k]
    for (int i = tid; i < BT * NOBS / 4; i += 256) {
        int m  = i >> 5;
        int kq = i & 31;
        float4 v = *(const float4*)(obs + ((b0 + m) * NA + a) * NOBS + kq * 4);
        int k = kq * 4;
        aT[(k + 0) * PAD + m] = v.x;
        aT[(k + 1) * PAD + m] = v.y;
        aT[(k + 2) * PAD + m] = v.z;
        aT[(k + 3) * PAD + m] = v.w;
    }
    if (tid < NH1) bias[tid] = b1[a * NH1 + tid];
    __syncthreads();

    const int tm = tid >> 5;   // 0..7  -> rows m = tm*8 .. tm*8+7 (4 f32x2 pairs)
    const int tn = tid & 31;   // cols n = tn*4 .. tn*4+3

    const uint32_t aBase = sptr(aT) + tm * 8 * 4;
    const uint32_t bBase = sptr(Ws) + tn * 4 * 4;

    // GEMM1: x[64][128] = obsT^T @ W1  (init accumulators with bias)
    u64 acc[4][4];
#pragma unroll
    for (int j = 0; j < 4; j++) {
        u64 bb = pk2(bias[tn * 4 + j]);
#pragma unroll
        for (int p = 0; p < 4; p++) acc[p][j] = bb;
    }

#pragma unroll 4
    for (int k = 0; k < NOBS; k++) {
        u64 a0, a1, a2, a3;
        lds128_2x64(a0, a1, aBase + k * (PAD * 4));
        lds128_2x64(a2, a3, aBase + k * (PAD * 4) + 16);
        float4 bv; lds128_f4(bv, bBase + k * (NH1 * 4));
        u64 p0 = pk2(bv.x), p1 = pk2(bv.y), p2 = pk2(bv.z), p3 = pk2(bv.w);
        ffma2(acc[0][0], a0, p0); ffma2(acc[1][0], a1, p0);
        ffma2(acc[2][0], a2, p0); ffma2(acc[3][0], a3, p0);
        ffma2(acc[0][1], a0, p1); ffma2(acc[1][1], a1, p1);
        ffma2(acc[2][1], a2, p1); ffma2(acc[3][1], a3, p1);
        ffma2(acc[0][2], a0, p2); ffma2(acc[1][2], a1, p2);
        ffma2(acc[2][2], a2, p2); ffma2(acc[3][2], a3, p2);
        ffma2(acc[0][3], a0, p3); ffma2(acc[1][3], a1, p3);
        ffma2(acc[2][3], a2, p3); ffma2(acc[3][3], a3, p3);
    }
    __syncthreads();   // done reading aT / Ws

    // relu + transposed store xT[n][m] into aT (rows n = tn*4+j)
#pragma unroll
    for (int j = 0; j < 4; j++) {
        int n = tn * 4 + j;
        uint32_t sa = sptr(aT) + (n * PAD + tm * 8) * 4;
        sts128_2x64(sa,      relu2(acc[0][j]), relu2(acc[1][j]));
        sts128_2x64(sa + 16, relu2(acc[2][j]), relu2(acc[3][j]));
    }

    // Stage W2 [128][64] and b2
    {
        const float4* src = (const float4*)(W2 + a * NH1 * NHX);
        float4* dst = (float4*)Ws;
#pragma unroll
        for (int i = tid; i < NH1 * NHX / 4; i += 256) dst[i] = src[i];
    }
    if (tid < NHX) bias[tid] = b2[a * NHX + tid];
    __syncthreads();

    // GEMM2: h[64][64] = xT^T @ W2   (cols n = tn*2, tn*2+1)
    u64 acc2[4][2];
#pragma unroll
    for (int j = 0; j < 2; j++) {
        u64 bb = pk2(bias[tn * 2 + j]);
#pragma unroll
        for (int p = 0; p < 4; p++) acc2[p][j] = bb;
    }
    const uint32_t b2Base = sptr(Ws) + tn * 2 * 4;
#pragma unroll 4
    for (int k = 0; k < NH1; k++) {
        u64 a0, a1, a2, a3;
        lds128_2x64(a0, a1, aBase + k * (PAD * 4));
        lds128_2x64(a2, a3, aBase + k * (PAD * 4) + 16);
        float2 bv; lds64_f2(bv, b2Base + k * (NHX * 4));
        u64 p0 = pk2(bv.x), p1 = pk2(bv.y);
        ffma2(acc2[0][0], a0, p0); ffma2(acc2[1][0], a1, p0);
        ffma2(acc2[2][0], a2, p0); ffma2(acc2[3][0], a3, p0);
        ffma2(acc2[0][1], a0, p1); ffma2(acc2[1][1], a1, p1);
        ffma2(acc2[2][1], a2, p1); ffma2(acc2[3][1], a3, p1);
    }
    // relu + store h rows (coalesced float2 per row)
#pragma unroll
    for (int p = 0; p < 4; p++) {
        float2 f0 = up2(acc2[p][0]);
        float2 f1 = up2(acc2[p][1]);
        int m0 = b0 + tm * 8 + p * 2;
        float* r0 = g_h + ((size_t)m0 * NA + a) * NHX + tn * 2;
        float* r1 = g_h + ((size_t)(m0 + 1) * NA + a) * NHX + tn * 2;
        *(float2*)r0 = make_float2(fmaxf(f0.x, 0.0f), fmaxf(f1.x, 0.0f));
        *(float2*)r1 = make_float2(fmaxf(f0.y, 0.0f), fmaxf(f1.y, 0.0f));
    }
}

// ---------------------------------------------------------------------------
// Communication: comm[b,i,:] = sum_j M[i,j] * h[b,j,:]
// ---------------------------------------------------------------------------
__global__ __launch_bounds__(256) void k_comm() {
    __shared__ float hs[NA * NHX];
    const int tid = threadIdx.x;
    const int b = blockIdx.x;

    {
        const float4* src = (const float4*)(g_h + (size_t)b * NA * NHX);
        float4* dst = (float4*)hs;
#pragma unroll
        for (int i = tid; i < NA * NHX / 4; i += 256) dst[i] = src[i];
    }
    __syncthreads();

    const int lane = tid & 31;
    const int ig   = tid >> 5;     // warp -> agents i0..i0+3
    const int i0   = ig * 4;

    float mreg[4];
#pragma unroll
    for (int ii = 0; ii < 4; ii++) mreg[ii] = g_maskn[(i0 + ii) * NA + lane];

    u64 acc[4] = {0ull, 0ull, 0ull, 0ull};
    const uint32_t hBase = sptr(hs) + lane * 8;   // cols lane*2, lane*2+1
#pragma unroll
    for (int j = 0; j < NA; j++) {
        u64 hp;
        asm volatile("ld.shared.u64 %0, [%1];" : "=l"(hp) : "r"(hBase + j * (NHX * 4)));
#pragma unroll
        for (int ii = 0; ii < 4; ii++) {
            float mj = __shfl_sync(0xffffffffu, mreg[ii], j);
            ffma2(acc[ii], pk2(mj), hp);
        }
    }
#pragma unroll
    for (int ii = 0; ii < 4; ii++) {
        float2 f = up2(acc[ii]);
        *(float2*)(g_comm + ((size_t)b * NA + i0 + ii) * NHX + lane * 2) = f;
    }
}

// ---------------------------------------------------------------------------
// Final: h2 = tanh([h, comm]@Wc + bc); q = h2@Wd + bd
// ---------------------------------------------------------------------------
__global__ __launch_bounds__(256, 2) void k_final(
    const float* __restrict__ Wc, const float* __restrict__ bc,
    const float* __restrict__ Wd, const float* __restrict__ bd,
    float* __restrict__ q)
{
    extern __shared__ float sm[];
    float* Ws  = sm;                        // Wc: 128*64
    float* aT  = sm + 2 * NHX * NHX;        // 128 x PAD
    float* Wds = aT + 2 * NHX * PAD;        // 64*16
    float* bcs = Wds + NHX * NACT;          // 64
    float* bds = bcs + NHX;                 // 16

    const int tid = threadIdx.x;
    const int b0  = blockIdx.x * BT;
    const int a   = blockIdx.y;

    // Stage Wc [128][64]
    {
        const float4* src = (const float4*)(Wc + a * 2 * NHX * NHX);
        float4* dst = (float4*)Ws;
#pragma unroll
        for (int i = tid; i < 2 * NHX * NHX / 4; i += 256) dst[i] = src[i];
    }
    // Stage concat transposed: rows 0..63 = h, rows 64..127 = comm
    for (int i = tid; i < BT * NHX / 4; i += 256) {
        int m  = i >> 4;
        int kq = i & 15;
        int c = kq * 4;
        float4 v = *(const float4*)(g_h    + ((size_t)(b0 + m) * NA + a) * NHX + kq * 4);
        float4 w = *(const float4*)(g_comm + ((size_t)(b0 + m) * NA + a) * NHX + kq * 4);
        aT[(c + 0) * PAD + m] = v.x;  aT[(c + 1) * PAD + m] = v.y;
        aT[(c + 2) * PAD + m] = v.z;  aT[(c + 3) * PAD + m] = v.w;
        aT[(NHX + c + 0) * PAD + m] = w.x;  aT[(NHX + c + 1) * PAD + m] = w.y;
        aT[(NHX + c + 2) * PAD + m] = w.z;  aT[(NHX + c + 3) * PAD + m] = w.w;
    }
    {
        const float4* src = (const float4*)(Wd + a * NHX * NACT);
        float4* dst = (float4*)Wds;
#pragma unroll
        for (int i = tid; i < NHX * NACT / 4; i += 256) dst[i] = src[i];
    }
    if (tid < NHX)  bcs[tid] = bc[a * NHX + tid];
    if (tid < NACT) bds[tid] = bd[a * NACT + tid];
    __syncthreads();

    const int tm = tid >> 5;
    const int tn = tid & 31;
    const uint32_t aBase = sptr(aT) + tm * 8 * 4;
    const uint32_t bBase = sptr(Ws) + tn * 2 * 4;

    // GEMM3: pre[64][64] = concat^T @ Wc
    u64 acc[4][2];
#pragma unroll
    for (int j = 0; j < 2; j++) {
        u64 bb = pk2(bcs[tn * 2 + j]);
#pragma unroll
        for (int p = 0; p < 4; p++) acc[p][j] = bb;
    }
#pragma unroll 4
    for (int k = 0; k < 2 * NHX; k++) {
        u64 a0, a1, a2, a3;
        lds128_2x64(a0, a1, aBase + k * (PAD * 4));
        lds128_2x64(a2, a3, aBase + k * (PAD * 4) + 16);
        float2 bv; lds64_f2(bv, bBase + k * (NHX * 4));
        u64 p0 = pk2(bv.x), p1 = pk2(bv.y);
        ffma2(acc[0][0], a0, p0); ffma2(acc[1][0], a1, p0);
        ffma2(acc[2][0], a2, p0); ffma2(acc[3][0], a3, p0);
        ffma2(acc[0][1], a0, p1); ffma2(acc[1][1], a1, p1);
        ffma2(acc[2][1], a2, p1); ffma2(acc[3][1], a3, p1);
    }
    __syncthreads();   // done reading aT

    // tanh + transposed store h2T[n][m] into aT rows 0..63
#pragma unroll
    for (int j = 0; j < 2; j++) {
        int n = tn * 2 + j;
        uint32_t sa = sptr(aT) + (n * PAD + tm * 8) * 4;
        sts128_2x64(sa,      tanh2(acc[0][j]), tanh2(acc[1][j]));
        sts128_2x64(sa + 16, tanh2(acc[2][j]), tanh2(acc[3][j]));
    }
    __syncthreads();

    // GEMM4: q[64][16] = h2 @ Wd   (m = tid&63, warp-uniform n-group)
    const int m = tid & 63;
    const int g = tid >> 6;
    u64 acc4[2];
    acc4[0] = mk2(bds[g * 4 + 0], bds[g * 4 + 1]);
    acc4[1] = mk2(bds[g * 4 + 2], bds[g * 4 + 3]);
    const uint32_t a4 = sptr(aT) + m * 4;
    const uint32_t w4 = sptr(Wds) + g * 16;
#pragma unroll 8
    for (int k = 0; k < NHX; k++) {
        float av = aT[k * PAD + m];
        u64 ap = pk2(av);
        u64 w0, w1;
        lds128_2x64(w0, w1, w4 + k * (NACT * 4));
        ffma2(acc4[0], ap, w0);
        ffma2(acc4[1], ap, w1);
        (void)a4;
    }
    float2 f0 = up2(acc4[0]);
    float2 f1 = up2(acc4[1]);
    float4 outv = make_float4(f0.x, f0.y, f1.x, f1.y);
    *(float4*)(q + ((size_t)(b0 + m) * NA + a) * NACT + g * 4) = outv;
}

// ---------------------------------------------------------------------------
extern "C" void kernel_launch(void* const* d_in, const int* in_sizes, int n_in,
                              void* d_out, int out_size) {
    const float* obs = (const float*)d_in[0];
    const float* W1  = (const float*)d_in[1];
    const float* b1  = (const float*)d_in[2];
    const float* W2  = (const float*)d_in[3];
    const float* b2  = (const float*)d_in[4];
    // d_in[5], d_in[6]: Wg, bg — dead code (gates never reach the output)
    const float* Wc  = (const float*)d_in[7];
    const float* bc  = (const float*)d_in[8];
    const float* Wd  = (const float*)d_in[9];
    const float* bd  = (const float*)d_in[10];
    const int*   cm  = (const int*)d_in[11];
    float* q = (float*)d_out;

    const size_t smem_enc = (size_t)(NH1 * NOBS + NOBS * PAD + NH1) * sizeof(float);
    const size_t smem_fin = (size_t)(2 * NHX * NHX + 2 * NHX * PAD + NHX * NACT + NHX + NACT) * sizeof(float);

    cudaFuncSetAttribute(k_encode, cudaFuncAttributeMaxDynamicSharedMemorySize, (int)smem_enc);
    cudaFuncSetAttribute(k_final,  cudaFuncAttributeMaxDynamicSharedMemorySize, (int)smem_fin);

    k_mask<<<1, 32>>>(cm);
    k_encode<<<dim3(NB / BT, NA), 256, smem_enc>>>(obs, W1, b1, W2, b2);
    k_comm<<<NB, 256>>>();
    k_final<<<dim3(NB / BT, NA), 256, smem_fin>>>(Wc, bc, Wd, bd, q);
}